// round 7
// baseline (speedup 1.0000x reference)
#include <cuda_runtime.h>

// BackEdgeConv2d fused: out = x * !(5 <= boxcount7x7(x >= 128/255, reflect) <= 19)
// x: [16,3,1024,1024] fp32. 3 phases: pair-vectorized cond build (sign-bit pack),
// uint4 rolling vertical sums, SIMD prefix-sum horizontal with x-prefetch pipeline.

#define TILE_W 128
#define TILE_H 64
#define KPAD 3
#define PH (TILE_H + 2*KPAD)        // 70 padded rows
#define WPR 36                      // words per cond row (144 B, 16B-aligned rows)
#define ROWB 144
#define PPR 18                      // word-pairs per row
#define U4PR 9                      // uint4 per row
#define NTHREADS 256

// PTX prmt: guarantees default-mode semantics incl. selector-bit-3 MSB-replicate.
__device__ __forceinline__ unsigned prmt(unsigned a, unsigned b, unsigned s) {
    unsigned r;
    asm("prmt.b32 %0, %1, %2, %3;" : "=r"(r) : "r"(a), "r"(b), "r"(s));
    return r;
}

__global__ __launch_bounds__(NTHREADS, 7)
void backedge_kernel(const float* __restrict__ x, float* __restrict__ out,
                     int H, int W) {
    __shared__ __align__(16) unsigned int scond[PH * WPR];      // 10080 B
    __shared__ __align__(16) unsigned int svsum[TILE_H * WPR];  // 9216 B

    const int tid = threadIdx.x;
    const int c0 = blockIdx.x * TILE_W;
    const int r0 = blockIdx.y * TILE_H;
    const long long plane = (long long)blockIdx.z * H * W;
    const float* xp = x + plane;
    float* op = out + plane;
    const float T = 128.0f / 255.0f;

    // ---- Phase 1: padded cond map; one word-PAIR (8 px) per iteration.
    //      cond byte j of row <-> global col (c0 - 4 + j). Bytes >= 136 unused.
    #pragma unroll 1
    for (int t = tid; t < PH * PPR; t += NTHREADS) {
        int pr = t / PPR;                     // const divisor -> mul.hi
        int pw = t - pr * PPR;
        uint2 cw;
        if (pw == 17) {
            cw = make_uint2(0u, 0u);          // tail pad bytes 136..143
        } else {
            int gr = r0 + pr - KPAD;
            int gc = c0 + (pw << 3) - 4;
            float4 va, vb;
            if ((unsigned)gr < (unsigned)H && (unsigned)gc <= (unsigned)(W - 8)) {
                const float4* p = (const float4*)(xp + gr * W + gc);
                va = p[0]; vb = p[1];
            } else {
                int rr = gr < 0 ? -gr : (gr >= H ? 2 * H - 2 - gr : gr);
                const float* rowp = xp + rr * W;
                float f[8];
                #pragma unroll
                for (int k = 0; k < 8; k++) {
                    int g = gc + k;
                    g = g < 0 ? -g : (g >= W ? 2 * W - 2 - g : g);
                    f[k] = rowp[g];
                }
                va = make_float4(f[0], f[1], f[2], f[3]);
                vb = make_float4(f[4], f[5], f[6], f[7]);
            }
            // cond = (x >= T) = !signbit(x - T); x==T -> +0 -> cond 1 (exact).
            unsigned a0 = __float_as_uint(va.x - T), a1 = __float_as_uint(va.y - T);
            unsigned a2 = __float_as_uint(va.z - T), a3 = __float_as_uint(va.w - T);
            unsigned b0 = __float_as_uint(vb.x - T), b1 = __float_as_uint(vb.y - T);
            unsigned b2 = __float_as_uint(vb.z - T), b3 = __float_as_uint(vb.w - T);
            unsigned sa = prmt(prmt(a0, a1, 0x0073), prmt(a2, a3, 0x0073), 0x5410);
            unsigned sb = prmt(prmt(b0, b1, 0x0073), prmt(b2, b3, 0x0073), 0x5410);
            cw.x = ((~sa) & 0x80808080u) >> 7;    // 1/0 per byte
            cw.y = ((~sb) & 0x80808080u) >> 7;
        }
        ((uint2*)scond)[t] = cw;              // uint2 index == t (18 pairs/row)
    }
    __syncthreads();

    // ---- Phase 2: vertical 7-sum, rolling 4-row bands, uint4 byte-SIMD.
    //      144 tasks = 16 bands x 9 uint4-cols; threads 0..143 take one each.
    if (tid < (TILE_H / 4) * U4PR) {
        int band = tid / U4PR;
        int col  = tid - band * U4PR;
        int rb = band << 2;
        const uint4* base = (const uint4*)scond + col;
        uint4* v4 = (uint4*)svsum + col;
        uint4 s = base[rb * U4PR];
        #pragma unroll
        for (int k = 1; k < 7; k++) {
            uint4 a = base[(rb + k) * U4PR];
            s.x += a.x; s.y += a.y; s.z += a.z; s.w += a.w;
        }
        v4[rb * U4PR] = s;
        #pragma unroll
        for (int j = 1; j < 4; j++) {
            uint4 ad = base[(rb + 6 + j) * U4PR];
            uint4 su = base[(rb + j - 1) * U4PR];
            s.x += ad.x - su.x;  s.y += ad.y - su.y;   // byte-exact (mod 2^32 assoc.)
            s.z += ad.z - su.z;  s.w += ad.w - su.w;
            v4[(rb + j) * U4PR] = s;
        }
    }
    __syncthreads();

    // ---- Phase 3: 8 px/thread/row, SIMD prefix sums, x prefetched 1 block ahead.
    const int tx = tid & 15;                  // -> output px cols c0+8tx .. +7
    const int ty = tid >> 4;                  // 16 rows per block, 4 blocks
    const int span = tx << 3;                 // byte offset in row
    const unsigned char* vsb = (const unsigned char*)svsum;
    const int stepv = 4 * W;                  // 16 rows in float4 units

    const float4* gx = (const float4*)(xp + (r0 + ty) * W + c0 + span);
    float4* go = (float4*)(op + (r0 + ty) * W + c0 + span);
    float4 xa = gx[0], xb = gx[1];

    #pragma unroll
    for (int i = 0; i < 4; i++) {
        const int r = (i << 4) + ty;
        const uint2* vs = (const uint2*)(vsb + r * ROWB + span);
        uint2 lo = vs[0], hi = vs[1];

        float4 na, nb;
        if (i < 3) {                          // prefetch next row-block's x
            na = gx[(i + 1) * stepv];
            nb = gx[(i + 1) * stepv + 1];
        }

        // byte prefix sums P[0..15] of the 16-byte span (max 112 < 256)
        unsigned p0 = lo.x * 0x01010101u;
        unsigned p1 = lo.y * 0x01010101u + prmt(p0, 0, 0x3333);
        unsigned p2 = hi.x * 0x01010101u + prmt(p1, 0, 0x3333);
        unsigned p3 = hi.y * 0x01010101u + prmt(p2, 0, 0x3333);
        unsigned hA = __vsub4(prmt(p1, p2, 0x6543), p0);   // px 0..3
        unsigned hB = __vsub4(prmt(p2, p3, 0x6543), p1);   // px 4..7

        // band 5..19 per byte -> MSB flag (h <= 49, no cross-byte carry)
        unsigned mA = (hA + 0x7B7B7B7Bu) & ~(hA + 0x6C6C6C6Cu) & 0x80808080u;
        unsigned mB = (hB + 0x7B7B7B7Bu) & ~(hB + 0x6C6C6C6Cu) & 0x80808080u;

        float4 oa, ob;
        oa.x = __uint_as_float(__float_as_uint(xa.x) & ~prmt(mA, 0, 0x8888));
        oa.y = __uint_as_float(__float_as_uint(xa.y) & ~prmt(mA, 0, 0x9999));
        oa.z = __uint_as_float(__float_as_uint(xa.z) & ~prmt(mA, 0, 0xAAAA));
        oa.w = __uint_as_float(__float_as_uint(xa.w) & ~prmt(mA, 0, 0xBBBB));
        ob.x = __uint_as_float(__float_as_uint(xb.x) & ~prmt(mB, 0, 0x8888));
        ob.y = __uint_as_float(__float_as_uint(xb.y) & ~prmt(mB, 0, 0x9999));
        ob.z = __uint_as_float(__float_as_uint(xb.z) & ~prmt(mB, 0, 0xAAAA));
        ob.w = __uint_as_float(__float_as_uint(xb.w) & ~prmt(mB, 0, 0xBBBB));

        __stcs(go + i * stepv,     oa);
        __stcs(go + i * stepv + 1, ob);

        xa = na; xb = nb;
    }
}

extern "C" void kernel_launch(void* const* d_in, const int* in_sizes, int n_in,
                              void* d_out, int out_size) {
    const float* x = (const float*)d_in[0];
    float* out = (float*)d_out;
    const int H = 1024, W = 1024;
    const int planes = out_size / (H * W);   // B*C = 48
    dim3 grid(W / TILE_W, H / TILE_H, planes);
    backedge_kernel<<<grid, NTHREADS>>>(x, out, H, W);
}

// round 8
// speedup vs baseline: 1.1820x; 1.1820x over previous
#include <cuda_runtime.h>

// BackEdgeConv2d fused: out = x * !(5 <= boxcount7x7(x >= 128/255, reflect) <= 19)
// x: [16,3,1024,1024] fp32. R3 skeleton (proven): 3 phases, TILE 128x64.
// R8: phase-1 interior-CTA fast path + sign-bit cond pack. Phases 2/3 = R3.

#define TILE_W 128
#define TILE_H 64
#define KPAD 3
#define PH (TILE_H + 2*KPAD)        // 70 padded rows
#define WPR 34                      // 136 cond bytes/row: byte j <-> global col c0-4+j
#define W2PR 17                     // uint2 per row
#define NTHREADS 256

// PTX prmt: guaranteed default-mode semantics (byte gather).
__device__ __forceinline__ unsigned prmt(unsigned a, unsigned b, unsigned s) {
    unsigned r;
    asm("prmt.b32 %0, %1, %2, %3;" : "=r"(r) : "r"(a), "r"(b), "r"(s));
    return r;
}

__global__ __launch_bounds__(NTHREADS)
void backedge_kernel(const float* __restrict__ x, float* __restrict__ out,
                     int H, int W) {
    __shared__ __align__(16) unsigned int scond[PH * WPR];      // 9520 B
    __shared__ __align__(16) unsigned int svsum[TILE_H * WPR];  // 8704 B

    const int tid = threadIdx.x;
    const int c0 = blockIdx.x * TILE_W;
    const int r0 = blockIdx.y * TILE_H;
    const long long plane = (long long)blockIdx.z * H * W;
    const float* xp = x + plane;
    float* op = out + plane;
    const float T = 128.0f / 255.0f;

    // ---- Phase 1: padded binary cond map, one uint32 word (4 px) per iter.
    //      cond = (x >= T) = !signbit(x - T): RN keeps sign for tiny negatives,
    //      x == T -> +0 -> cond 1. Exact.
    const bool interior = (c0 >= 4) && (c0 + TILE_W + 4 <= W) &&
                          (r0 >= KPAD) && (r0 + TILE_H + KPAD <= H);
    if (interior) {
        const float* base = xp + (r0 - KPAD) * W + (c0 - 4);
        #pragma unroll 1
        for (int wi = tid; wi < PH * WPR; wi += NTHREADS) {
            int pr = wi / WPR;                // const divisor -> mul.hi
            int w  = wi - pr * WPR;
            const float4 v = *(const float4*)(base + pr * W + (w << 2));
            unsigned a0 = __float_as_uint(v.x - T);
            unsigned a1 = __float_as_uint(v.y - T);
            unsigned a2 = __float_as_uint(v.z - T);
            unsigned a3 = __float_as_uint(v.w - T);
            unsigned sa = prmt(prmt(a0, a1, 0x0073), prmt(a2, a3, 0x0073), 0x5410);
            scond[wi] = ((~sa) & 0x80808080u) >> 7;     // 1/0 per byte
        }
    } else {
        #pragma unroll 1
        for (int wi = tid; wi < PH * WPR; wi += NTHREADS) {
            int pr = wi / WPR;
            int w  = wi - pr * WPR;
            int gr = r0 + pr - KPAD;
            int gc = c0 + (w << 2) - 4;
            float4 v;
            if ((unsigned)gr < (unsigned)H && (unsigned)gc <= (unsigned)(W - 4)) {
                v = *(const float4*)(xp + gr * W + gc);
            } else {
                int rr = gr < 0 ? -gr : (gr >= H ? 2 * H - 2 - gr : gr);
                const float* rowp = xp + rr * W;
                int g0 = gc, g1 = gc + 1, g2 = gc + 2, g3 = gc + 3;
                g0 = g0 < 0 ? -g0 : (g0 >= W ? 2 * W - 2 - g0 : g0);
                g1 = g1 < 0 ? -g1 : (g1 >= W ? 2 * W - 2 - g1 : g1);
                g2 = g2 < 0 ? -g2 : (g2 >= W ? 2 * W - 2 - g2 : g2);
                g3 = g3 < 0 ? -g3 : (g3 >= W ? 2 * W - 2 - g3 : g3);
                v.x = rowp[g0]; v.y = rowp[g1]; v.z = rowp[g2]; v.w = rowp[g3];
            }
            unsigned a0 = __float_as_uint(v.x - T);
            unsigned a1 = __float_as_uint(v.y - T);
            unsigned a2 = __float_as_uint(v.z - T);
            unsigned a3 = __float_as_uint(v.w - T);
            unsigned sa = prmt(prmt(a0, a1, 0x0073), prmt(a2, a3, 0x0073), 0x5410);
            scond[wi] = ((~sa) & 0x80808080u) >> 7;
        }
    }
    __syncthreads();

    // ---- Phase 2: vertical 7-sum, SIMD bytes, 8 px (uint2) per iteration (== R3)
    {
        const uint2* c2 = (const uint2*)scond;
        uint2* v2 = (uint2*)svsum;
        #pragma unroll 1
        for (int wi = tid; wi < TILE_H * W2PR; wi += NTHREADS) {
            uint2 s = c2[wi];
            #pragma unroll
            for (int k = 1; k < 7; k++) {
                uint2 a = c2[wi + k * W2PR];
                s.x += a.x; s.y += a.y;
            }
            v2[wi] = s;
        }
    }
    __syncthreads();

    // ---- Phase 3: horizontal sliding 7-sum via dp4a, 4 px/thread/row (== R3)
    const int tx = tid & 31;        // word group -> cols [4tx .. 4tx+3]
    const int ty = tid >> 5;
    #pragma unroll
    for (int rr = 0; rr < TILE_H; rr += 8) {
        const int r = ty + rr;
        const unsigned int* row = &svsum[r * WPR];
        unsigned int w0 = row[tx];
        unsigned int w1 = row[tx + 1];
        unsigned int w2 = row[tx + 2];

        // window bytes a1..a10 of the 12-byte span starting at byte 4*tx
        int h0 = __dp4a(w0, 0x01010100u, 0u);           // a1+a2+a3
        h0 = __dp4a(w1, 0x01010101u, (unsigned)h0);     // + a4..a7
        int a1  = (w0 >> 8)  & 0xFF;
        int a2  = (w0 >> 16) & 0xFF;
        int a3  = (w0 >> 24) & 0xFF;
        int a8  =  w2        & 0xFF;
        int a9  = (w2 >> 8)  & 0xFF;
        int a10 = (w2 >> 16) & 0xFF;
        int h1 = h0 - a1 + a8;
        int h2 = h1 - a2 + a9;
        int h3 = h2 - a3 + a10;

        const float* gp = xp + (long long)(r0 + r) * W + c0 + (tx << 2);
        float4 xv = *(const float4*)gp;
        float4 ov;
        ov.x = ((unsigned)(h0 - 5) <= 14u) ? 0.0f : xv.x;   // band 5..19 inclusive
        ov.y = ((unsigned)(h1 - 5) <= 14u) ? 0.0f : xv.y;
        ov.z = ((unsigned)(h2 - 5) <= 14u) ? 0.0f : xv.z;
        ov.w = ((unsigned)(h3 - 5) <= 14u) ? 0.0f : xv.w;

        __stcs((float4*)&op[(long long)(r0 + r) * W + c0 + (tx << 2)], ov);
    }
}

extern "C" void kernel_launch(void* const* d_in, const int* in_sizes, int n_in,
                              void* d_out, int out_size) {
    const float* x = (const float*)d_in[0];
    float* out = (float*)d_out;
    const int H = 1024, W = 1024;
    const int planes = out_size / (H * W);   // B*C = 48
    dim3 grid(W / TILE_W, H / TILE_H, planes);
    backedge_kernel<<<grid, NTHREADS>>>(x, out, H, W);
}